// round 8
// baseline (speedup 1.0000x reference)
#include <cuda_runtime.h>
#include <cuda_fp16.h>
#include <math.h>
#include <stdint.h>

#define BSZ 2
#define SEQ 2048
#define EMB 768
#define NH 12
#define HDIM 64
#define ROWS (BSZ*SEQ)

// Q/K fp16 [B*H][seq][d-permuted]; V fp16 transposed [B*H][d][seq-permuted].
// Permutation within each 16-group: logical (2i,2i+1,2i+8,2i+9) stored at phys 4i..4i+3.
__device__ __half g_q1h[BSZ*NH*SEQ*HDIM];
__device__ __half g_k1h[BSZ*NH*SEQ*HDIM];
__device__ __half g_vth[BSZ*NH*SEQ*HDIM];
__device__ __half g_q2h[BSZ*NH*SEQ*HDIM];
__device__ __half g_k2h[BSZ*NH*SEQ*HDIM];
__device__ float g_att[ROWS*EMB];
__device__ float g_rms[ROWS];

// ---------------------------------------------------------------------------
__device__ __forceinline__ float ex2f(float x) {
    float y;
    asm("ex2.approx.f32 %0, %1;" : "=f"(y) : "f"(x));
    return y;
}
__device__ __forceinline__ void mma16(float* c, const uint32_t* a, uint32_t b0, uint32_t b1) {
    asm volatile(
        "mma.sync.aligned.m16n8k16.row.col.f32.f16.f16.f32 "
        "{%0,%1,%2,%3},{%4,%5,%6,%7},{%8,%9},{%0,%1,%2,%3};"
        : "+f"(c[0]), "+f"(c[1]), "+f"(c[2]), "+f"(c[3])
        : "r"(a[0]), "r"(a[1]), "r"(a[2]), "r"(a[3]), "r"(b0), "r"(b1));
}
__device__ __forceinline__ uint32_t pack_h2(float lo, float hi) {
    __half2 h = __float22half2_rn(make_float2(lo, hi));
    return *(uint32_t*)&h;
}
#define CP16(dst_u32, src_ptr) \
    asm volatile("cp.async.cg.shared.global [%0], [%1], 16;" :: "r"(dst_u32), "l"(src_ptr))
#define CPCOMMIT() asm volatile("cp.async.commit_group;")

// 0.125 * log2(e): fold head-dim scale AND exp->exp2 conversion into Q
#define QSCALE 0.18033688011112042f

// ---------------------------------------------------------------------------
// Merged QKV projection GEMM, fp16 m16n8k16, register-prefetch double buffer.
// grid (30, 32): bx<18 -> W1, bx>=18 -> W2 (first 1536 cols; v2 dead).
// ---------------------------------------------------------------------------
__global__ __launch_bounds__(256) void qkv_mma_kernel(const float* __restrict__ X,
                                                      const float* __restrict__ W1,
                                                      const float* __restrict__ W2)
{
    __shared__ __half As[128*48];
    __shared__ __half Bs[128*48];

    const int tid  = threadIdx.x;
    const int lane = tid & 31, warp = tid >> 5;
    const int g = lane >> 2, tig = lane & 3;
    const int wm = warp >> 1, wn = warp & 1;
    const int m0 = blockIdx.y * 128;
    const bool second = blockIdx.x >= 18;
    const float* __restrict__ W = second ? W2 : W1;
    const int n0 = (second ? blockIdx.x - 18 : blockIdx.x) * 128;

    float acc[2][8][4] = {};
    float4 ra[4], rb[4];

    // prefetch kk=0 into registers
    #pragma unroll
    for (int it = 0; it < 4; it++) {
        int i = tid + it * 256;
        int rowA = i >> 3, cA = i & 7;
        ra[it] = *(const float4*)(X + (size_t)(m0 + rowA) * EMB + 4 * cA);
        int n = i & 127, kg = i >> 7;
        const float* wp = W + (size_t)(4 * kg) * 2304 + n0 + n;
        rb[it] = make_float4(wp[0], wp[2304], wp[2 * 2304], wp[3 * 2304]);
    }

    for (int kk = 0; kk < EMB; kk += 32) {
        // STS (convert + permute)
        #pragma unroll
        for (int it = 0; it < 4; it++) {
            int i = tid + it * 256;
            int rowA = i >> 3, c = i & 7;
            int q = c & 3;
            int baseA = rowA * 48 + (c >> 2) * 16;
            int p1 = (q & 1) * 8 + (q >> 1) * 2;
            *(uint32_t*)&As[baseA + p1]     = pack_h2(ra[it].x, ra[it].y);
            *(uint32_t*)&As[baseA + p1 + 4] = pack_h2(ra[it].z, ra[it].w);
            int n = i & 127, kg = i >> 7;
            int qb = kg & 3;
            int baseB = n * 48 + (kg >> 2) * 16;
            int p2 = (qb & 1) * 8 + (qb >> 1) * 2;
            *(uint32_t*)&Bs[baseB + p2]     = pack_h2(rb[it].x, rb[it].y);
            *(uint32_t*)&Bs[baseB + p2 + 4] = pack_h2(rb[it].z, rb[it].w);
        }
        __syncthreads();

        if (kk + 32 < EMB) {
            #pragma unroll
            for (int it = 0; it < 4; it++) {
                int i = tid + it * 256;
                int rowA = i >> 3, cA = i & 7;
                ra[it] = *(const float4*)(X + (size_t)(m0 + rowA) * EMB + kk + 32 + 4 * cA);
                int n = i & 127, kg = i >> 7;
                const float* wp = W + (size_t)(kk + 32 + 4 * kg) * 2304 + n0 + n;
                rb[it] = make_float4(wp[0], wp[2304], wp[2 * 2304], wp[3 * 2304]);
            }
        }

        #pragma unroll
        for (int s = 0; s < 2; s++) {
            uint32_t a[2][4];
            #pragma unroll
            for (int mt = 0; mt < 2; mt++) {
                int row = 32 * wm + 16 * mt;
                uint2 u = *(uint2*)&As[(row + g)     * 48 + 16 * s + 4 * tig];
                uint2 v = *(uint2*)&As[(row + g + 8) * 48 + 16 * s + 4 * tig];
                a[mt][0] = u.x; a[mt][1] = v.x; a[mt][2] = u.y; a[mt][3] = v.y;
            }
            #pragma unroll
            for (int t = 0; t < 8; t++) {
                uint2 bb = *(uint2*)&Bs[(64 * wn + 8 * t + g) * 48 + 16 * s + 4 * tig];
                mma16(acc[0][t], a[0], bb.x, bb.y);
                mma16(acc[1][t], a[1], bb.x, bb.y);
            }
        }
        __syncthreads();
    }

    const int cbase = n0 + 64 * wn;
    const int sel = cbase / EMB;
    const int h = (cbase - sel * EMB) >> 6;
    const int bb = m0 >> 11;

    if (!second && sel == 2) {
        __half* vt = g_vth + (size_t)(bb * NH + h) * HDIM * SEQ;
        #pragma unroll
        for (int mt = 0; mt < 2; mt++) {
            int rbw = (m0 & (SEQ - 1)) + 32 * wm + 16 * mt;
            int n1p = rbw + 4 * (g >> 1) + (g & 1);
            #pragma unroll
            for (int t = 0; t < 8; t++) {
                int d0 = 8 * t + 2 * tig;
                vt[(size_t)d0 * SEQ + n1p]           = __float2half_rn(acc[mt][t][0]);
                vt[(size_t)(d0 + 1) * SEQ + n1p]     = __float2half_rn(acc[mt][t][1]);
                vt[(size_t)d0 * SEQ + n1p + 2]       = __float2half_rn(acc[mt][t][2]);
                vt[(size_t)(d0 + 1) * SEQ + n1p + 2] = __float2half_rn(acc[mt][t][3]);
            }
        }
    } else {
        __half* dst = second ? (sel == 0 ? g_q2h : g_k2h)
                             : (sel == 0 ? g_q1h : g_k1h);
        const float scl = (sel == 0) ? QSCALE : 1.0f;
        #pragma unroll
        for (int mt = 0; mt < 2; mt++) {
            int n = (m0 + 32 * wm + 16 * mt + g) & (SEQ - 1);
            size_t base = (size_t)(bb * NH + h) * SEQ;
            #pragma unroll
            for (int t = 0; t < 8; t++) {
                int dphys = 16 * (t >> 1) + 4 * tig + 2 * (t & 1);
                *(uint32_t*)&dst[(base + n) * HDIM + dphys] =
                    pack_h2(acc[mt][t][0] * scl, acc[mt][t][1] * scl);
                *(uint32_t*)&dst[(base + n + 8) * HDIM + dphys] =
                    pack_h2(acc[mt][t][2] * scl, acc[mt][t][3] * scl);
            }
        }
    }
}

// ---------------------------------------------------------------------------
// Differential flash attention, fp16 mma, 512 threads (16 warps), k-split.
// P stays in registers. Single barrier per k-iter:
//   sync -> prefetch(next, other buf) -> wait(1) -> compute(cur buf)
// smem (halfs): Q2 0 (128x80), K1 10240 (2x64x80), K2 20480, V 30720 (2x64x80).
// ---------------------------------------------------------------------------
__global__ __launch_bounds__(512) void diff_attn_fp16(const float* __restrict__ lam1,
                                                      const float* __restrict__ lam2)
{
    extern __shared__ __align__(16) char smraw[];
    __half* smh = (__half*)smraw;
    const int Q2H = 0, K1H = 10240, K2H = 20480, VH = 30720;

    const int tid  = threadIdx.x;
    const int lane = tid & 31, warp = tid >> 5;
    const int g = lane >> 2, tig = lane & 3;
    const int qg = warp & 7, kh = warp >> 3;
    const int r = 16 * qg;
    const int bh = blockIdx.y;
    const int b = bh / NH, h = bh - b * NH;
    const int q0 = blockIdx.x * 128;

    const __half* Q1g = g_q1h + ((size_t)bh * SEQ + q0) * HDIM;
    const __half* Q2g = g_q2h + ((size_t)bh * SEQ + q0) * HDIM;
    const __half* K1g = g_k1h + (size_t)bh * SEQ * HDIM;
    const __half* K2g = g_k2h + (size_t)bh * SEQ * HDIM;
    const __half* Vtg = g_vth + (size_t)bh * HDIM * SEQ;

    // Q2 tile -> smem raw copy (perm preserved), stride 80 halfs
    #pragma unroll
    for (int it = 0; it < 2; it++) {
        int i = tid + it * 512;
        int row = i >> 3, c = i & 7;
        *(uint4*)&smh[Q2H + row * 80 + c * 8] = *(const uint4*)(Q2g + row * 64 + c * 8);
    }
    // Q1 fragments -> registers
    uint32_t q1f[4][4];
    #pragma unroll
    for (int s = 0; s < 4; s++) {
        uint2 u = *(const uint2*)(Q1g + (r + g)     * 64 + 16 * s + 4 * tig);
        uint2 v = *(const uint2*)(Q1g + (r + g + 8) * 64 + 16 * s + 4 * tig);
        q1f[s][0] = u.x; q1f[s][1] = v.x; q1f[s][2] = u.y; q1f[s][3] = v.y;
    }

    const uint32_t smb = (uint32_t)__cvta_generic_to_shared(smraw);

    // one commit group per k-tile: K1 + K2 + V
    auto prefetch_KV = [&](int kt, int buf) {
        int row = tid >> 3, c = tid & 7;
        CP16(smb + (uint32_t)(K1H + buf * 5120 + row * 80 + c * 8) * 2,
             K1g + (size_t)kt * 4096 + row * 64 + c * 8);
        CP16(smb + (uint32_t)(K2H + buf * 5120 + row * 80 + c * 8) * 2,
             K2g + (size_t)kt * 4096 + row * 64 + c * 8);
        CP16(smb + (uint32_t)(VH + buf * 5120 + row * 80 + c * 8) * 2,
             Vtg + (size_t)row * SEQ + kt * 64 + c * 8);
        CPCOMMIT();
    };

    prefetch_KV(0, 0);

    float o1[8][4] = {}, o2[8][4] = {};
    float l1[2] = {0.f, 0.f}, l2[2] = {0.f, 0.f};

    const int NT = SEQ / 64;
    for (int kt = 0; kt < NT; kt++) {
        const int cur = kt & 1;
        const bool more = (kt + 1 < NT);

        __syncthreads();                 // all warps done reading buf(cur^1)
        if (more) {
            prefetch_KV(kt + 1, cur ^ 1);
            asm volatile("cp.async.wait_group 1;");   // group(cur) complete
        } else {
            asm volatile("cp.async.wait_group 0;");
        }
        __syncthreads();                 // data visibility for all warps

        const int K1c = K1H + cur * 5120;
        const int K2c = K2H + cur * 5120;
        const int Vc  = VH  + cur * 5120;

        uint32_t pa1[2][4], pa2[2][4];
        // ---- attn1: S1 = Q1 K1^T; exp -> PV A-fragments in registers ----
        {
            float s1[4][4] = {};
            #pragma unroll
            for (int s = 0; s < 4; s++) {
                #pragma unroll
                for (int t = 0; t < 4; t++) {
                    int kr = 32 * kh + 8 * t + g;
                    uint2 kb = *(uint2*)&smh[K1c + kr * 80 + 16 * s + 4 * tig];
                    mma16(s1[t], q1f[s], kb.x, kb.y);
                }
            }
            #pragma unroll
            for (int t = 0; t < 4; t++) {
                float p0 = ex2f(s1[t][0]);
                float p1 = ex2f(s1[t][1]);
                float p2 = ex2f(s1[t][2]);
                float p3 = ex2f(s1[t][3]);
                l1[0] += p0 + p1;
                l1[1] += p2 + p3;
                pa1[t >> 1][2 * (t & 1)]     = pack_h2(p0, p1);
                pa1[t >> 1][2 * (t & 1) + 1] = pack_h2(p2, p3);
            }
        }
        // ---- attn2 ----
        {
            float s2[4][4] = {};
            #pragma unroll
            for (int s = 0; s < 4; s++) {
                uint32_t aq[4];
                uint2 u = *(uint2*)&smh[Q2H + (r + g)     * 80 + 16 * s + 4 * tig];
                uint2 v = *(uint2*)&smh[Q2H + (r + g + 8) * 80 + 16 * s + 4 * tig];
                aq[0] = u.x; aq[1] = v.x; aq[2] = u.y; aq[3] = v.y;
                #pragma unroll
                for (int t = 0; t < 4; t++) {
                    int kr = 32 * kh + 8 * t + g;
                    uint2 kb = *(uint2*)&smh[K2c + kr * 80 + 16 * s + 4 * tig];
                    mma16(s2[t], aq, kb.x, kb.y);
                }
            }
            #pragma unroll
            for (int t = 0; t < 4; t++) {
                float p0 = ex2f(s2[t][0]);
                float p1 = ex2f(s2[t][1]);
                float p2 = ex2f(s2[t][2]);
                float p3 = ex2f(s2[t][3]);
                l2[0] += p0 + p1;
                l2[1] += p2 + p3;
                pa2[t >> 1][2 * (t & 1)]     = pack_h2(p0, p1);
                pa2[t >> 1][2 * (t & 1) + 1] = pack_h2(p2, p3);
            }
        }

        // ---- O += P @ V ----
        #pragma unroll
        for (int s2 = 0; s2 < 2; s2++) {
            #pragma unroll
            for (int t = 0; t < 8; t++) {
                int vr = 8 * t + g;
                uint2 vb = *(uint2*)&smh[Vc + vr * 80 + 32 * kh + 16 * s2 + 4 * tig];
                mma16(o1[t], pa1[s2], vb.x, vb.y);
                mma16(o2[t], pa2[s2], vb.x, vb.y);
            }
        }
    }

    // ---- final reduction across tig lanes (l) and kh warp pairs (l, O) ----
    #pragma unroll
    for (int rr = 0; rr < 2; rr++) {
        l1[rr] += __shfl_xor_sync(0xffffffffu, l1[rr], 1);
        l1[rr] += __shfl_xor_sync(0xffffffffu, l1[rr], 2);
        l2[rr] += __shfl_xor_sync(0xffffffffu, l2[rr], 1);
        l2[rr] += __shfl_xor_sync(0xffffffffu, l2[rr], 2);
    }
    __syncthreads();                     // done reading Q2/K/V; reuse as scratch
    float* ob1 = (float*)smraw;          // 128x68 f32
    float* ob2 = ob1 + 8704;
    float* lbuf = ob2 + 8704;            // 256 f32
    if (kh == 1) {
        #pragma unroll
        for (int t = 0; t < 8; t++) {
            *(float2*)&ob1[(r + g)     * 68 + 8 * t + 2 * tig] = make_float2(o1[t][0], o1[t][1]);
            *(float2*)&ob1[(r + g + 8) * 68 + 8 * t + 2 * tig] = make_float2(o1[t][2], o1[t][3]);
            *(float2*)&ob2[(r + g)     * 68 + 8 * t + 2 * tig] = make_float2(o2[t][0], o2[t][1]);
            *(float2*)&ob2[(r + g + 8) * 68 + 8 * t + 2 * tig] = make_float2(o2[t][2], o2[t][3]);
        }
        if (tig == 0) {
            lbuf[r + g]           = l1[0];
            lbuf[r + g + 8]       = l1[1];
            lbuf[128 + r + g]     = l2[0];
            lbuf[128 + r + g + 8] = l2[1];
        }
    }
    __syncthreads();
    if (kh == 0) {
        const float lam = lam1[h] - lam2[h] + 0.1f;
        const float i10 = 1.f / (l1[0] + lbuf[r + g]);
        const float i11 = 1.f / (l1[1] + lbuf[r + g + 8]);
        const float i20 = 1.f / (l2[0] + lbuf[128 + r + g]);
        const float i21 = 1.f / (l2[1] + lbuf[128 + r + g + 8]);
        const int n = q0 + r + g;
        #pragma unroll
        for (int t = 0; t < 8; t++) {
            const int col = h * HDIM + 8 * t + 2 * tig;
            float2 p10 = *(float2*)&ob1[(r + g)     * 68 + 8 * t + 2 * tig];
            float2 p11 = *(float2*)&ob1[(r + g + 8) * 68 + 8 * t + 2 * tig];
            float2 p20 = *(float2*)&ob2[(r + g)     * 68 + 8 * t + 2 * tig];
            float2 p21 = *(float2*)&ob2[(r + g + 8) * 68 + 8 * t + 2 * tig];
            float2 r0 = make_float2((o1[t][0] + p10.x) * i10 - lam * (o2[t][0] + p20.x) * i20,
                                    (o1[t][1] + p10.y) * i10 - lam * (o2[t][1] + p20.y) * i20);
            float2 r1 = make_float2((o1[t][2] + p11.x) * i11 - lam * (o2[t][2] + p21.x) * i21,
                                    (o1[t][3] + p11.y) * i11 - lam * (o2[t][3] + p21.y) * i21);
            *(float2*)&g_att[((size_t)(b * SEQ + n)) * EMB + col]     = r0;
            *(float2*)&g_att[((size_t)(b * SEQ + n + 8)) * EMB + col] = r1;
        }
    }
}

// ---------------------------------------------------------------------------
// Per-row inverse RMS (warp per row)
// ---------------------------------------------------------------------------
__global__ void rms_kernel()
{
    const int lane = threadIdx.x & 31, warp = threadIdx.x >> 5;
    const int row = blockIdx.x * 8 + warp;
    const float* p = g_att + (size_t)row * EMB;
    float ss = 0.f;
    #pragma unroll
    for (int i = 0; i < 6; i++) {
        float4 v = *(const float4*)(p + lane * 4 + i * 128);
        ss += v.x * v.x + v.y * v.y + v.z * v.z + v.w * v.w;
    }
    #pragma unroll
    for (int off = 16; off > 0; off >>= 1)
        ss += __shfl_xor_sync(0xffffffffu, ss, off);
    if (lane == 0) g_rms[row] = rsqrtf(ss * (1.0f / EMB) + 1e-6f);
}

// ---------------------------------------------------------------------------
// Output projection with fused RMSNorm, fp16 mma, 128x128 tile, 256 threads,
// register-prefetch double buffer: out = (att*rms*nw) @ Wp + bias
// ---------------------------------------------------------------------------
__global__ __launch_bounds__(256) void proj_mma_kernel(const float* __restrict__ W,
                                                       const float* __restrict__ bias,
                                                       const float* __restrict__ nw,
                                                       float* __restrict__ out)
{
    __shared__ __half As[128*48];
    __shared__ __half Bs[128*48];

    const int tid  = threadIdx.x;
    const int lane = tid & 31, warp = tid >> 5;
    const int g = lane >> 2, tig = lane & 3;
    const int wm = warp >> 1, wn = warp & 1;
    const int m0 = blockIdx.y * 128, n0 = blockIdx.x * 128;

    float acc[2][8][4] = {};
    float rmsr[4];
    #pragma unroll
    for (int it = 0; it < 4; it++)
        rmsr[it] = g_rms[m0 + ((tid + it * 256) >> 3)];

    float4 ra[4], rn[4], rb[4];
    #pragma unroll
    for (int it = 0; it < 4; it++) {
        int i = tid + it * 256;
        int rowA = i >> 3, cA = i & 7;
        ra[it] = *(const float4*)(g_att + (size_t)(m0 + rowA) * EMB + 4 * cA);
        rn[it] = *(const float4*)(nw + 4 * cA);
        int n = i & 127, kg = i >> 7;
        const float* wp = W + (size_t)(4 * kg) * EMB + n0 + n;
        rb[it] = make_float4(wp[0], wp[EMB], wp[2 * EMB], wp[3 * EMB]);
    }

    for (int kk = 0; kk < EMB; kk += 32) {
        #pragma unroll
        for (int it = 0; it < 4; it++) {
            int i = tid + it * 256;
            int rowA = i >> 3, c = i & 7;
            int q = c & 3;
            int baseA = rowA * 48 + (c >> 2) * 16;
            int p1 = (q & 1) * 8 + (q >> 1) * 2;
            *(uint32_t*)&As[baseA + p1] =
                pack_h2(ra[it].x * rmsr[it] * rn[it].x, ra[it].y * rmsr[it] * rn[it].y);
            *(uint32_t*)&As[baseA + p1 + 4] =
                pack_h2(ra[it].z * rmsr[it] * rn[it].z, ra[it].w * rmsr[it] * rn[it].w);
            int n = i & 127, kg = i >> 7;
            int qb = kg & 3;
            int baseB = n * 48 + (kg >> 2) * 16;
            int p2 = (qb & 1) * 8 + (qb >> 1) * 2;
            *(uint32_t*)&Bs[baseB + p2]     = pack_h2(rb[it].x, rb[it].y);
            *(uint32_t*)&Bs[baseB + p2 + 4] = pack_h2(rb[it].z, rb[it].w);
        }
        __syncthreads();

        if (kk + 32 < EMB) {
            #pragma unroll
            for (int it = 0; it < 4; it++) {
                int i = tid + it * 256;
                int rowA = i >> 3, cA = i & 7;
                ra[it] = *(const float4*)(g_att + (size_t)(m0 + rowA) * EMB + kk + 32 + 4 * cA);
                rn[it] = *(const float4*)(nw + kk + 32 + 4 * cA);
                int n = i & 127, kg = i >> 7;
                const float* wp = W + (size_t)(kk + 32 + 4 * kg) * EMB + n0 + n;
                rb[it] = make_float4(wp[0], wp[EMB], wp[2 * EMB], wp[3 * EMB]);
            }
        }

        #pragma unroll
        for (int s = 0; s < 2; s++) {
            uint32_t a[2][4];
            #pragma unroll
            for (int mt = 0; mt < 2; mt++) {
                int row = 32 * wm + 16 * mt;
                uint2 u = *(uint2*)&As[(row + g)     * 48 + 16 * s + 4 * tig];
                uint2 v = *(uint2*)&As[(row + g + 8) * 48 + 16 * s + 4 * tig];
                a[mt][0] = u.x; a[mt][1] = v.x; a[mt][2] = u.y; a[mt][3] = v.y;
            }
            #pragma unroll
            for (int t = 0; t < 8; t++) {
                uint2 bb = *(uint2*)&Bs[(64 * wn + 8 * t + g) * 48 + 16 * s + 4 * tig];
                mma16(acc[0][t], a[0], bb.x, bb.y);
                mma16(acc[1][t], a[1], bb.x, bb.y);
            }
        }
        __syncthreads();
    }

    #pragma unroll
    for (int mt = 0; mt < 2; mt++) {
        int row0 = m0 + 32 * wm + 16 * mt + g;
        #pragma unroll
        for (int t = 0; t < 8; t++) {
            int c = n0 + 64 * wn + 8 * t + 2 * tig;
            float2 r0 = make_float2(acc[mt][t][0] + bias[c], acc[mt][t][1] + bias[c + 1]);
            float2 r1 = make_float2(acc[mt][t][2] + bias[c], acc[mt][t][3] + bias[c + 1]);
            *(float2*)&out[(size_t)row0 * EMB + c]       = r0;
            *(float2*)&out[(size_t)(row0 + 8) * EMB + c] = r1;
        }
    }
}

extern "C" void kernel_launch(void* const* d_in, const int* in_sizes, int n_in,
                              void* d_out, int out_size)
{
    const float* x  = (const float*)d_in[0];
    const float* W1 = (const float*)d_in[1];
    const float* W2 = (const float*)d_in[2];
    const float* Wp = (const float*)d_in[3];
    const float* bp = (const float*)d_in[4];
    const float* nw = (const float*)d_in[5];
    const float* l1 = (const float*)d_in[6];
    const float* l2 = (const float*)d_in[7];
    // d_in[8] = xpos (int64) unused: attention is non-causal in the reference
    float* out = (float*)d_out;

    qkv_mma_kernel<<<dim3(30, 32), 256>>>(x, W1, W2);

    const size_t smem = 40960u * 2;   // 81920 B
    cudaFuncSetAttribute(diff_attn_fp16, cudaFuncAttributeMaxDynamicSharedMemorySize, (int)smem);
    diff_attn_fp16<<<dim3(SEQ / 128, BSZ * NH), 512, smem>>>(l1, l2);

    rms_kernel<<<ROWS / 8, 256>>>();
    proj_mma_kernel<<<dim3(EMB / 128, ROWS / 128), 256>>>(Wp, bp, nw, out);
}